// round 15
// baseline (speedup 1.0000x reference)
#include <cuda_runtime.h>
#include <cuda_bf16.h>
#include <math.h>

#define N_USERS 50000
#define N_ENT   100000
#define DIMS    64
#define N_REL   16
#define E_KG    1500000
#define E_IN    1000000
#define RSQRT_DK 0.17677669529663687f   /* 1/sqrt(32) */

#define NB_ENT (N_ENT / 8)     /* 12500 entity blocks (8 warps = 8 rows each) */
#define NB_USR (N_USERS / 8)   /*  6250 user blocks */

// scan tiling: 1024 threads x 4 elems = 4096 per tile
#define KG_TILES 25            /* ceil(100000/4096) */
#define IU_TILES 13            /* ceil(50000/4096)  */
#define II_TILES 25
#define TOT_TILES (KG_TILES + IU_TILES + II_TILES)   /* 63 */

// ---------------- static device scratch (no runtime allocation) ----------------
__device__ __nv_bfloat162 g_P[N_ENT * 32];   // entity_emb @ W_Q, bf16 (scores only)
__device__ float g_ent0[N_ENT * DIMS];       // layer-1 entity output
__device__ float g_usr0[N_USERS * DIMS];     // layer-1 user output

// CSR structures (built once per call)
__device__ int g_kg_row[N_ENT + 1];
__device__ int g_kg_cnt[N_ENT];
__device__ unsigned g_kg_pk[E_KG];           // tail | (rel<<20)
__device__ int g_kg_rk[E_KG];                // rank within head bucket
__device__ int g_iu_row[N_USERS + 1];
__device__ int g_iu_cnt[N_USERS];
__device__ int2 g_iu_pk[E_IN];               // {item, w bits}
__device__ int g_iu_rk[E_IN];
__device__ int g_ii_row[N_ENT + 1];
__device__ int g_ii_cnt[N_ENT];
__device__ int2 g_ii_pk[E_IN];               // {user, w bits}
__device__ int g_ii_rk[E_IN];
__device__ int g_bsum[TOT_TILES];

// ---------------- CSR build ----------------
__global__ void zero_cnt_k(int* __restrict__ a, int na, int* __restrict__ b, int nb,
                           int* __restrict__ c, int nc) {
    int i = blockIdx.x * blockDim.x + threadIdx.x;
    int stride = gridDim.x * blockDim.x;
    int nab = na + nb, tot = nab + nc;
    for (; i < tot; i += stride) {
        if (i < na) a[i] = 0;
        else if (i < nab) b[i - na] = 0;
        else c[i - nab] = 0;
    }
}

// Histogram + rank: atomicAdd returns this edge's rank within its bucket.
__global__ void hist_k(const int* __restrict__ eidx, const int* __restrict__ iedge,
                       int* __restrict__ kg_cnt, int* __restrict__ kg_rk,
                       int* __restrict__ iu_cnt, int* __restrict__ iu_rk,
                       int* __restrict__ ii_cnt, int* __restrict__ ii_rk) {
    int stride = gridDim.x * blockDim.x * 4;
    for (int base = (blockIdx.x * blockDim.x + threadIdx.x) * 4; base < E_KG;
         base += stride) {
        int4 h = *(const int4*)&eidx[base];
        int4 r;
        r.x = atomicAdd(&kg_cnt[h.x], 1);
        r.y = atomicAdd(&kg_cnt[h.y], 1);
        r.z = atomicAdd(&kg_cnt[h.z], 1);
        r.w = atomicAdd(&kg_cnt[h.w], 1);
        *(int4*)&kg_rk[base] = r;
    }
    for (int base = (blockIdx.x * blockDim.x + threadIdx.x) * 4; base < E_IN;
         base += stride) {
        int4 u  = *(const int4*)&iedge[base];
        int4 it = *(const int4*)&iedge[E_IN + base];
        int4 r1, r2;
        r1.x = atomicAdd(&iu_cnt[u.x], 1);
        r1.y = atomicAdd(&iu_cnt[u.y], 1);
        r1.z = atomicAdd(&iu_cnt[u.z], 1);
        r1.w = atomicAdd(&iu_cnt[u.w], 1);
        r2.x = atomicAdd(&ii_cnt[it.x], 1);
        r2.y = atomicAdd(&ii_cnt[it.y], 1);
        r2.z = atomicAdd(&ii_cnt[it.z], 1);
        r2.w = atomicAdd(&ii_cnt[it.w], 1);
        *(int4*)&iu_rk[base] = r1;
        *(int4*)&ii_rk[base] = r2;
    }
}

// decode tile block -> (cnt, row, n, tile)
__device__ __forceinline__ void scan_decode(int b, const int* kg_cnt, int* kg_row,
                                            const int* iu_cnt, int* iu_row,
                                            const int* ii_cnt, int* ii_row,
                                            const int** cnt, int** row,
                                            int* n, int* tile) {
    if (b < KG_TILES)                { *cnt = kg_cnt; *row = kg_row; *n = N_ENT;   *tile = b; }
    else if (b < KG_TILES + IU_TILES){ *cnt = iu_cnt; *row = iu_row; *n = N_USERS; *tile = b - KG_TILES; }
    else                             { *cnt = ii_cnt; *row = ii_row; *n = N_ENT;   *tile = b - KG_TILES - IU_TILES; }
}

// Phase A: per-tile sums.
__global__ void __launch_bounds__(1024) scanA_k(const int* __restrict__ kg_cnt,
                                                int* __restrict__ kg_row,
                                                const int* __restrict__ iu_cnt,
                                                int* __restrict__ iu_row,
                                                const int* __restrict__ ii_cnt,
                                                int* __restrict__ ii_row,
                                                int* __restrict__ bsum) {
    const int* cnt; int* row; int n, tile;
    scan_decode(blockIdx.x, kg_cnt, kg_row, iu_cnt, iu_row, ii_cnt, ii_row,
                &cnt, &row, &n, &tile);
    __shared__ int wsum[32];
    int tid = threadIdx.x, lane = tid & 31, w = tid >> 5;
    int i = tile * 4096 + tid * 4;
    int4 v = (i < n) ? *(const int4*)&cnt[i] : make_int4(0, 0, 0, 0);
    int tsum = v.x + v.y + v.z + v.w;
    #pragma unroll
    for (int o = 16; o; o >>= 1) tsum += __shfl_xor_sync(0xffffffffu, tsum, o);
    if (lane == 0) wsum[w] = tsum;
    __syncthreads();
    if (w == 0) {
        int s = wsum[lane];
        #pragma unroll
        for (int o = 16; o; o >>= 1) s += __shfl_xor_sync(0xffffffffu, s, o);
        if (lane == 0) bsum[blockIdx.x] = s;
    }
}

// Phase C: per-tile exclusive scan; segment base computed inline by reducing
// the preceding tiles' sums (<= 25 values, one warp). Last tile writes row[n].
__global__ void __launch_bounds__(1024) scanC_k(const int* __restrict__ kg_cnt,
                                                int* __restrict__ kg_row,
                                                const int* __restrict__ iu_cnt,
                                                int* __restrict__ iu_row,
                                                const int* __restrict__ ii_cnt,
                                                int* __restrict__ ii_row,
                                                const int* __restrict__ bsum) {
    const int* cnt; int* row; int n, tile;
    scan_decode(blockIdx.x, kg_cnt, kg_row, iu_cnt, iu_row, ii_cnt, ii_row,
                &cnt, &row, &n, &tile);
    __shared__ int wsum[32];
    __shared__ int sbase;
    int tid = threadIdx.x, lane = tid & 31, w = tid >> 5;
    if (tid < 32) {
        int v = (tid < tile) ? bsum[blockIdx.x - tile + tid] : 0;
        #pragma unroll
        for (int o = 16; o; o >>= 1) v += __shfl_xor_sync(0xffffffffu, v, o);
        if (tid == 0) sbase = v;
    }
    int i = tile * 4096 + tid * 4;
    int4 v = (i < n) ? *(const int4*)&cnt[i] : make_int4(0, 0, 0, 0);
    int tsum = v.x + v.y + v.z + v.w;
    int x = tsum;
    #pragma unroll
    for (int o = 1; o < 32; o <<= 1) {
        int y = __shfl_up_sync(0xffffffffu, x, o);
        if (lane >= o) x += y;
    }
    if (lane == 31) wsum[w] = x;
    __syncthreads();
    if (w == 0) {
        int s = wsum[lane];
        #pragma unroll
        for (int o = 1; o < 32; o <<= 1) {
            int y = __shfl_up_sync(0xffffffffu, s, o);
            if (lane >= o) s += y;
        }
        wsum[lane] = s;
    }
    __syncthreads();
    int excl = x - tsum + (w ? wsum[w - 1] : 0) + sbase;
    if (i < n) {
        int4 o4 = make_int4(excl, excl + v.x, excl + v.x + v.y,
                            excl + v.x + v.y + v.z);
        *(int4*)&row[i] = o4;
    }
    int ntiles = (n + 4095) >> 12;
    if (tile == ntiles - 1 && tid == 1023)
        row[n] = sbase + wsum[31];
}

// Atomic-free scatter: position = row[node] + precomputed rank.
__global__ void scatter_k(const int* __restrict__ eidx, const int* __restrict__ etype,
                          const int* __restrict__ iedge, const float* __restrict__ iw,
                          const int* __restrict__ kg_row, const int* __restrict__ kg_rk,
                          unsigned* __restrict__ kg_pk,
                          const int* __restrict__ iu_row, const int* __restrict__ iu_rk,
                          int2* __restrict__ iu_pk,
                          const int* __restrict__ ii_row, const int* __restrict__ ii_rk,
                          int2* __restrict__ ii_pk) {
    int stride = gridDim.x * blockDim.x * 4;
    for (int base = (blockIdx.x * blockDim.x + threadIdx.x) * 4; base < E_KG;
         base += stride) {
        int4 hd = *(const int4*)&eidx[base];
        int4 tl = *(const int4*)&eidx[E_KG + base];
        int4 rt = *(const int4*)&etype[base];
        int4 rk = *(const int4*)&kg_rk[base];
        int p0 = kg_row[hd.x] + rk.x;
        int p1 = kg_row[hd.y] + rk.y;
        int p2 = kg_row[hd.z] + rk.z;
        int p3 = kg_row[hd.w] + rk.w;
        kg_pk[p0] = (unsigned)tl.x | ((unsigned)(rt.x - 1) << 20);
        kg_pk[p1] = (unsigned)tl.y | ((unsigned)(rt.y - 1) << 20);
        kg_pk[p2] = (unsigned)tl.z | ((unsigned)(rt.z - 1) << 20);
        kg_pk[p3] = (unsigned)tl.w | ((unsigned)(rt.w - 1) << 20);
    }
    for (int base = (blockIdx.x * blockDim.x + threadIdx.x) * 4; base < E_IN;
         base += stride) {
        int4 u   = *(const int4*)&iedge[base];
        int4 it  = *(const int4*)&iedge[E_IN + base];
        float4 w = *(const float4*)&iw[base];
        int4 r1  = *(const int4*)&iu_rk[base];
        int4 r2  = *(const int4*)&ii_rk[base];
        int a0 = iu_row[u.x] + r1.x;
        int a1 = iu_row[u.y] + r1.y;
        int a2 = iu_row[u.z] + r1.z;
        int a3 = iu_row[u.w] + r1.w;
        int b0 = ii_row[it.x] + r2.x;
        int b1 = ii_row[it.y] + r2.y;
        int b2 = ii_row[it.z] + r2.z;
        int b3 = ii_row[it.w] + r2.w;
        iu_pk[a0] = make_int2(it.x, __float_as_int(w.x));
        iu_pk[a1] = make_int2(it.y, __float_as_int(w.y));
        iu_pk[a2] = make_int2(it.z, __float_as_int(w.z));
        iu_pk[a3] = make_int2(it.w, __float_as_int(w.w));
        ii_pk[b0] = make_int2(u.x, __float_as_int(w.x));
        ii_pk[b1] = make_int2(u.y, __float_as_int(w.y));
        ii_pk[b2] = make_int2(u.z, __float_as_int(w.z));
        ii_pk[b3] = make_int2(u.w, __float_as_int(w.w));
    }
}

// ---------------- per-layer kernels ----------------
// P[r,:] = X[r,:] @ W (64x64), output bf16. 256 threads = 16 rows x 16 col-quads.
__global__ void __launch_bounds__(256) gemm_k(const float* __restrict__ X,
                                              const float* __restrict__ W,
                                              __nv_bfloat162* __restrict__ P) {
    __shared__ float sW[64 * 64];
    __shared__ float srow[16][64];
    int tid = threadIdx.x;
    #pragma unroll
    for (int i = 0; i < 16; i++) sW[tid + i * 256] = W[tid + i * 256];
    const float4* X4 = (const float4*)(X + (size_t)blockIdx.x * 16 * 64);
    ((float4*)&srow[0][0])[tid] = X4[tid];
    __syncthreads();
    int r  = tid >> 4;
    int cq = (tid & 15) * 4;
    float4 acc = make_float4(0.f, 0.f, 0.f, 0.f);
    #pragma unroll
    for (int d = 0; d < 64; d++) {
        float a = srow[r][d];
        float4 b = *(const float4*)&sW[d * 64 + cq];
        acc.x += a * b.x; acc.y += a * b.y; acc.z += a * b.z; acc.w += a * b.w;
    }
    size_t o = ((size_t)blockIdx.x * 16 + r) * 32 + (cq >> 1);
    P[o]     = __float22bfloat162_rn(make_float2(acc.x, acc.y));
    P[o + 1] = __float22bfloat162_rn(make_float2(acc.z, acc.w));
}

__device__ __forceinline__ float4 ld_P4(const __nv_bfloat162* __restrict__ P,
                                        int row, int l) {
    uint2 raw = *(const uint2*)(P + (size_t)row * 32 + l * 2);
    __nv_bfloat162 b0 = *(__nv_bfloat162*)&raw.x;
    __nv_bfloat162 b1 = *(__nv_bfloat162*)&raw.y;
    float2 f0 = __bfloat1622float2(b0);
    float2 f1 = __bfloat1622float2(b1);
    return make_float4(f0.x, f0.y, f1.x, f1.y);
}

// Fused node update with index prefetch. Blocks [0, NB_ENT) entities,
// [NB_ENT, NB_ENT+NB_USR) users. One warp per row; lanes 0-15 edge j,
// lanes 16-31 edge j+1; lane owns dims 4*(lane&15)..+3.
template <int FINAL>
__global__ void __launch_bounds__(256) node_k(const int* __restrict__ kg_row,
                                              const unsigned* __restrict__ kg_pk,
                                              const int* __restrict__ ii_row,
                                              const int2* __restrict__ ii_pk,
                                              const int* __restrict__ iu_row,
                                              const int2* __restrict__ iu_pk,
                                              const __nv_bfloat162* __restrict__ P,
                                              const float* __restrict__ ent_cur,
                                              const float* __restrict__ usr_cur,
                                              const float* __restrict__ relemb,
                                              const float* __restrict__ ent_p0,
                                              const float* __restrict__ usr_p0,
                                              float* __restrict__ ent_out,
                                              float* __restrict__ usr_out) {
    int tid  = threadIdx.x;
    int lane = tid & 31;
    int half = lane >> 4;
    int l    = lane & 15;
    int d0   = l * 4;
    const float c3 = 1.0f / 3.0f;

    if (blockIdx.x < NB_ENT) {
        // ---------------- entity path ----------------
        __shared__ float srel[N_REL * DIMS];
        #pragma unroll
        for (int i = 0; i < 4; i++) srel[tid + i * 256] = relemb[tid + i * 256];
        __syncthreads();

        int row = blockIdx.x * 8 + (tid >> 5);
        float4 ph = ld_P4(P, row, l);

        float4 acc = make_float4(0.f, 0.f, 0.f, 0.f);
        float ssum = 0.f;
        int s = kg_row[row], e = kg_row[row + 1];
        if (s < e) {
            int i0 = s + half;
            unsigned pk = kg_pk[i0 < e ? i0 : (e - 1)];
            for (int j = s; j < e; j += 2) {
                int nj = j + 2 + half;
                unsigned pk_n = kg_pk[nj < e ? nj : (e - 1)];   // prefetch
                bool valid = (j + half) < e;
                int tl = (int)(pk & 0xFFFFFu);
                int rt = (int)(pk >> 20);
                float4 pt = ld_P4(P, tl, l);
                float4 rv = *(const float4*)&srel[rt * 64 + d0];
                float4 te = *(const float4*)&ent_cur[(size_t)tl * 64 + d0];
                float part = ph.x * pt.x * rv.x + ph.y * pt.y * rv.y
                           + ph.z * pt.z * rv.z + ph.w * pt.w * rv.w;
                part += __shfl_xor_sync(0xffffffffu, part, 1);
                part += __shfl_xor_sync(0xffffffffu, part, 2);
                part += __shfl_xor_sync(0xffffffffu, part, 4);
                float ex = valid ? __expf(part * RSQRT_DK) : 0.f;
                ssum += ex;
                acc.x += ex * te.x * rv.x;
                acc.y += ex * te.y * rv.y;
                acc.z += ex * te.z * rv.z;
                acc.w += ex * te.w * rv.w;
                pk = pk_n;
            }
        }
        acc.x += __shfl_xor_sync(0xffffffffu, acc.x, 16);
        acc.y += __shfl_xor_sync(0xffffffffu, acc.y, 16);
        acc.z += __shfl_xor_sync(0xffffffffu, acc.z, 16);
        acc.w += __shfl_xor_sync(0xffffffffu, acc.w, 16);
        ssum  += __shfl_xor_sync(0xffffffffu, ssum, 16);

        float invs = (ssum > 0.f) ? (1.f / ssum) : 1.f;
        acc.x *= invs; acc.y *= invs; acc.z *= invs; acc.w *= invs;

        float s2 = acc.x * acc.x + acc.y * acc.y + acc.z * acc.z + acc.w * acc.w;
        s2 += __shfl_xor_sync(0xffffffffu, s2, 1);
        s2 += __shfl_xor_sync(0xffffffffu, s2, 2);
        s2 += __shfl_xor_sync(0xffffffffu, s2, 4);
        s2 += __shfl_xor_sync(0xffffffffu, s2, 8);
        float invn = 1.0f / fmaxf(sqrtf(s2), 1e-12f);
        acc.x *= invn; acc.y *= invn; acc.z *= invn; acc.w *= invn;

        // user -> entity aggregation (pair-split, prefetched)
        float4 acc2 = make_float4(0.f, 0.f, 0.f, 0.f);
        int si = ii_row[row], ei = ii_row[row + 1];
        if (si < ei) {
            int i0 = si + half;
            int2 pc = ii_pk[i0 < ei ? i0 : (ei - 1)];
            for (int k = si; k < ei; k += 2) {
                int nk = k + 2 + half;
                int2 pn = ii_pk[nk < ei ? nk : (ei - 1)];       // prefetch
                bool valid = (k + half) < ei;
                float w = valid ? __int_as_float(pc.y) : 0.f;
                float4 uv = *(const float4*)&usr_cur[(size_t)pc.x * 64 + d0];
                acc2.x += w * uv.x; acc2.y += w * uv.y;
                acc2.z += w * uv.z; acc2.w += w * uv.w;
                pc = pn;
            }
        }
        acc2.x += __shfl_xor_sync(0xffffffffu, acc2.x, 16);
        acc2.y += __shfl_xor_sync(0xffffffffu, acc2.y, 16);
        acc2.z += __shfl_xor_sync(0xffffffffu, acc2.z, 16);
        acc2.w += __shfl_xor_sync(0xffffffffu, acc2.w, 16);
        acc.x += acc2.x; acc.y += acc2.y; acc.z += acc2.z; acc.w += acc2.w;

        if (half == 0) {
            if (FINAL) {
                float4 a0 = *(const float4*)&ent_cur[(size_t)row * 64 + d0];
                float4 a1 = *(const float4*)&ent_p0[(size_t)row * 64 + d0];
                acc.x = (a0.x + a1.x + acc.x) * c3;
                acc.y = (a0.y + a1.y + acc.y) * c3;
                acc.z = (a0.z + a1.z + acc.z) * c3;
                acc.w = (a0.w + a1.w + acc.w) * c3;
            }
            *(float4*)&ent_out[(size_t)row * 64 + d0] = acc;
        }
    } else {
        // ---------------- user path ----------------
        int row = (blockIdx.x - NB_ENT) * 8 + (tid >> 5);
        float4 acc = make_float4(0.f, 0.f, 0.f, 0.f);
        int s = iu_row[row], e = iu_row[row + 1];
        if (s < e) {
            int i0 = s + half;
            int2 pc = iu_pk[i0 < e ? i0 : (e - 1)];
            for (int k = s; k < e; k += 2) {
                int nk = k + 2 + half;
                int2 pn = iu_pk[nk < e ? nk : (e - 1)];          // prefetch
                bool valid = (k + half) < e;
                float w = valid ? __int_as_float(pc.y) : 0.f;
                float4 ev = *(const float4*)&ent_cur[(size_t)pc.x * 64 + d0];
                acc.x += w * ev.x; acc.y += w * ev.y;
                acc.z += w * ev.z; acc.w += w * ev.w;
                pc = pn;
            }
        }
        acc.x += __shfl_xor_sync(0xffffffffu, acc.x, 16);
        acc.y += __shfl_xor_sync(0xffffffffu, acc.y, 16);
        acc.z += __shfl_xor_sync(0xffffffffu, acc.z, 16);
        acc.w += __shfl_xor_sync(0xffffffffu, acc.w, 16);

        if (half == 0) {
            if (FINAL) {
                float4 a0 = *(const float4*)&usr_cur[(size_t)row * 64 + d0];
                float4 a1 = *(const float4*)&usr_p0[(size_t)row * 64 + d0];
                acc.x = (a0.x + a1.x + acc.x) * c3;
                acc.y = (a0.y + a1.y + acc.y) * c3;
                acc.z = (a0.z + a1.z + acc.z) * c3;
                acc.w = (a0.w + a1.w + acc.w) * c3;
            }
            *(float4*)&usr_out[(size_t)row * 64 + d0] = acc;
        }
    }
}

// ---------------- launcher ----------------
extern "C" void kernel_launch(void* const* d_in, const int* in_sizes, int n_in,
                              void* d_out, int out_size) {
    const float* user_emb   = (const float*)d_in[1];
    const float* entity_emb = (const float*)d_in[2];
    const int*   inter_edge = (const int*)d_in[3];
    const float* inter_w    = (const float*)d_in[4];
    const int*   edge_index = (const int*)d_in[5];
    const int*   edge_type  = (const int*)d_in[6];
    const float* rel_emb    = (const float*)d_in[7];
    const float* W_Q        = (const float*)d_in[8];
    float* out = (float*)d_out;
    float* out_usr = out;
    float* out_ent = out + (size_t)N_USERS * DIMS;

    __nv_bfloat162* p_P;
    float *p_ent0, *p_usr0;
    int *p_kg_row, *p_kg_cnt, *p_kg_rk, *p_iu_row, *p_iu_cnt, *p_iu_rk;
    int *p_ii_row, *p_ii_cnt, *p_ii_rk, *p_bsum;
    unsigned* p_kg_pk;
    int2 *p_iu_pk, *p_ii_pk;
    cudaGetSymbolAddress((void**)&p_P,      g_P);
    cudaGetSymbolAddress((void**)&p_ent0,   g_ent0);
    cudaGetSymbolAddress((void**)&p_usr0,   g_usr0);
    cudaGetSymbolAddress((void**)&p_kg_row, g_kg_row);
    cudaGetSymbolAddress((void**)&p_kg_cnt, g_kg_cnt);
    cudaGetSymbolAddress((void**)&p_kg_pk,  g_kg_pk);
    cudaGetSymbolAddress((void**)&p_kg_rk,  g_kg_rk);
    cudaGetSymbolAddress((void**)&p_iu_row, g_iu_row);
    cudaGetSymbolAddress((void**)&p_iu_cnt, g_iu_cnt);
    cudaGetSymbolAddress((void**)&p_iu_pk,  g_iu_pk);
    cudaGetSymbolAddress((void**)&p_iu_rk,  g_iu_rk);
    cudaGetSymbolAddress((void**)&p_ii_row, g_ii_row);
    cudaGetSymbolAddress((void**)&p_ii_cnt, g_ii_cnt);
    cudaGetSymbolAddress((void**)&p_ii_pk,  g_ii_pk);
    cudaGetSymbolAddress((void**)&p_ii_rk,  g_ii_rk);
    cudaGetSymbolAddress((void**)&p_bsum,   g_bsum);

    const int TB = 256;
    const int NB_NODE = NB_ENT + NB_USR;   // 18750

    // ---- CSR build (shared by both layers) ----
    zero_cnt_k<<<512, TB>>>(p_kg_cnt, N_ENT, p_iu_cnt, N_USERS, p_ii_cnt, N_ENT);
    hist_k<<<2048, TB>>>(edge_index, inter_edge, p_kg_cnt, p_kg_rk,
                         p_iu_cnt, p_iu_rk, p_ii_cnt, p_ii_rk);
    scanA_k<<<TOT_TILES, 1024>>>(p_kg_cnt, p_kg_row, p_iu_cnt, p_iu_row,
                                 p_ii_cnt, p_ii_row, p_bsum);
    scanC_k<<<TOT_TILES, 1024>>>(p_kg_cnt, p_kg_row, p_iu_cnt, p_iu_row,
                                 p_ii_cnt, p_ii_row, p_bsum);
    scatter_k<<<2048, TB>>>(edge_index, edge_type, inter_edge, inter_w,
                            p_kg_row, p_kg_rk, p_kg_pk,
                            p_iu_row, p_iu_rk, p_iu_pk,
                            p_ii_row, p_ii_rk, p_ii_pk);

    // ---- layer 1 ----
    gemm_k<<<N_ENT / 16, TB>>>(entity_emb, W_Q, p_P);
    node_k<0><<<NB_NODE, TB>>>(p_kg_row, p_kg_pk, p_ii_row, p_ii_pk, p_iu_row, p_iu_pk,
                               p_P, entity_emb, user_emb, rel_emb,
                               nullptr, nullptr, p_ent0, p_usr0);

    // ---- layer 2 (writes the 3-layer mean directly to out) ----
    gemm_k<<<N_ENT / 16, TB>>>(p_ent0, W_Q, p_P);
    node_k<1><<<NB_NODE, TB>>>(p_kg_row, p_kg_pk, p_ii_row, p_ii_pk, p_iu_row, p_iu_pk,
                               p_P, p_ent0, p_usr0, rel_emb,
                               entity_emb, user_emb, out_ent, out_usr);
}

// round 16
// speedup vs baseline: 1.0006x; 1.0006x over previous
#include <cuda_runtime.h>
#include <cuda_bf16.h>
#include <math.h>

#define N_USERS 50000
#define N_ENT   100000
#define DIMS    64
#define N_REL   16
#define E_KG    1500000
#define E_IN    1000000
#define RSQRT_DK 0.17677669529663687f   /* 1/sqrt(32) */

#define NB_ENT (N_ENT / 8)     /* 12500 entity blocks (8 warps = 8 rows each) */
#define NB_USR (N_USERS / 8)   /*  6250 user blocks */

// scan tiling: 1024 threads x 4 elems = 4096 per tile
#define KG_TILES 25            /* ceil(100000/4096) */
#define IU_TILES 13            /* ceil(50000/4096)  */
#define II_TILES 25
#define TOT_TILES (KG_TILES + IU_TILES + II_TILES)   /* 63 */

// ---------------- static device scratch (no runtime allocation) ----------------
__device__ __nv_bfloat162 g_P[N_ENT * 32];   // entity_emb @ W_Q, bf16 (scores only)
__device__ float g_ent0[N_ENT * DIMS];       // layer-1 entity output
__device__ float g_usr0[N_USERS * DIMS];     // layer-1 user output

// CSR structures (built once per call)
__device__ int g_kg_row[N_ENT + 1];
__device__ int g_kg_cnt[N_ENT];
__device__ unsigned g_kg_pk[E_KG];           // tail | (rel<<20)
__device__ int g_kg_rk[E_KG];                // rank within head bucket
__device__ int g_iu_row[N_USERS + 1];
__device__ int g_iu_cnt[N_USERS];
__device__ int2 g_iu_pk[E_IN];               // {item, w bits}
__device__ int g_iu_rk[E_IN];
__device__ int g_ii_row[N_ENT + 1];
__device__ int g_ii_cnt[N_ENT];
__device__ int2 g_ii_pk[E_IN];               // {user, w bits}
__device__ int g_ii_rk[E_IN];
__device__ int g_bsum[TOT_TILES];

// ---------------- CSR build ----------------
__global__ void zero_cnt_k(int* __restrict__ a, int na, int* __restrict__ b, int nb,
                           int* __restrict__ c, int nc) {
    int i = blockIdx.x * blockDim.x + threadIdx.x;
    int stride = gridDim.x * blockDim.x;
    int nab = na + nb, tot = nab + nc;
    for (; i < tot; i += stride) {
        if (i < na) a[i] = 0;
        else if (i < nab) b[i - na] = 0;
        else c[i - nab] = 0;
    }
}

// Histogram + rank: atomicAdd returns this edge's rank within its bucket.
__global__ void hist_k(const int* __restrict__ eidx, const int* __restrict__ iedge,
                       int* __restrict__ kg_cnt, int* __restrict__ kg_rk,
                       int* __restrict__ iu_cnt, int* __restrict__ iu_rk,
                       int* __restrict__ ii_cnt, int* __restrict__ ii_rk) {
    int stride = gridDim.x * blockDim.x * 4;
    for (int base = (blockIdx.x * blockDim.x + threadIdx.x) * 4; base < E_KG;
         base += stride) {
        int4 h = *(const int4*)&eidx[base];
        int4 r;
        r.x = atomicAdd(&kg_cnt[h.x], 1);
        r.y = atomicAdd(&kg_cnt[h.y], 1);
        r.z = atomicAdd(&kg_cnt[h.z], 1);
        r.w = atomicAdd(&kg_cnt[h.w], 1);
        *(int4*)&kg_rk[base] = r;
    }
    for (int base = (blockIdx.x * blockDim.x + threadIdx.x) * 4; base < E_IN;
         base += stride) {
        int4 u  = *(const int4*)&iedge[base];
        int4 it = *(const int4*)&iedge[E_IN + base];
        int4 r1, r2;
        r1.x = atomicAdd(&iu_cnt[u.x], 1);
        r1.y = atomicAdd(&iu_cnt[u.y], 1);
        r1.z = atomicAdd(&iu_cnt[u.z], 1);
        r1.w = atomicAdd(&iu_cnt[u.w], 1);
        r2.x = atomicAdd(&ii_cnt[it.x], 1);
        r2.y = atomicAdd(&ii_cnt[it.y], 1);
        r2.z = atomicAdd(&ii_cnt[it.z], 1);
        r2.w = atomicAdd(&ii_cnt[it.w], 1);
        *(int4*)&iu_rk[base] = r1;
        *(int4*)&ii_rk[base] = r2;
    }
}

// decode tile block -> (cnt, row, n, tile)
__device__ __forceinline__ void scan_decode(int b, const int* kg_cnt, int* kg_row,
                                            const int* iu_cnt, int* iu_row,
                                            const int* ii_cnt, int* ii_row,
                                            const int** cnt, int** row,
                                            int* n, int* tile) {
    if (b < KG_TILES)                { *cnt = kg_cnt; *row = kg_row; *n = N_ENT;   *tile = b; }
    else if (b < KG_TILES + IU_TILES){ *cnt = iu_cnt; *row = iu_row; *n = N_USERS; *tile = b - KG_TILES; }
    else                             { *cnt = ii_cnt; *row = ii_row; *n = N_ENT;   *tile = b - KG_TILES - IU_TILES; }
}

// Phase A: per-tile sums.
__global__ void __launch_bounds__(1024) scanA_k(const int* __restrict__ kg_cnt,
                                                int* __restrict__ kg_row,
                                                const int* __restrict__ iu_cnt,
                                                int* __restrict__ iu_row,
                                                const int* __restrict__ ii_cnt,
                                                int* __restrict__ ii_row,
                                                int* __restrict__ bsum) {
    const int* cnt; int* row; int n, tile;
    scan_decode(blockIdx.x, kg_cnt, kg_row, iu_cnt, iu_row, ii_cnt, ii_row,
                &cnt, &row, &n, &tile);
    __shared__ int wsum[32];
    int tid = threadIdx.x, lane = tid & 31, w = tid >> 5;
    int i = tile * 4096 + tid * 4;
    int4 v = (i < n) ? *(const int4*)&cnt[i] : make_int4(0, 0, 0, 0);
    int tsum = v.x + v.y + v.z + v.w;
    #pragma unroll
    for (int o = 16; o; o >>= 1) tsum += __shfl_xor_sync(0xffffffffu, tsum, o);
    if (lane == 0) wsum[w] = tsum;
    __syncthreads();
    if (w == 0) {
        int s = wsum[lane];
        #pragma unroll
        for (int o = 16; o; o >>= 1) s += __shfl_xor_sync(0xffffffffu, s, o);
        if (lane == 0) bsum[blockIdx.x] = s;
    }
}

// Phase C: per-tile exclusive scan; segment base computed inline by reducing
// the preceding tiles' sums (<= 25 values, one warp). Last tile writes row[n].
__global__ void __launch_bounds__(1024) scanC_k(const int* __restrict__ kg_cnt,
                                                int* __restrict__ kg_row,
                                                const int* __restrict__ iu_cnt,
                                                int* __restrict__ iu_row,
                                                const int* __restrict__ ii_cnt,
                                                int* __restrict__ ii_row,
                                                const int* __restrict__ bsum) {
    const int* cnt; int* row; int n, tile;
    scan_decode(blockIdx.x, kg_cnt, kg_row, iu_cnt, iu_row, ii_cnt, ii_row,
                &cnt, &row, &n, &tile);
    __shared__ int wsum[32];
    __shared__ int sbase;
    int tid = threadIdx.x, lane = tid & 31, w = tid >> 5;
    if (tid < 32) {
        int v = (tid < tile) ? bsum[blockIdx.x - tile + tid] : 0;
        #pragma unroll
        for (int o = 16; o; o >>= 1) v += __shfl_xor_sync(0xffffffffu, v, o);
        if (tid == 0) sbase = v;
    }
    int i = tile * 4096 + tid * 4;
    int4 v = (i < n) ? *(const int4*)&cnt[i] : make_int4(0, 0, 0, 0);
    int tsum = v.x + v.y + v.z + v.w;
    int x = tsum;
    #pragma unroll
    for (int o = 1; o < 32; o <<= 1) {
        int y = __shfl_up_sync(0xffffffffu, x, o);
        if (lane >= o) x += y;
    }
    if (lane == 31) wsum[w] = x;
    __syncthreads();
    if (w == 0) {
        int s = wsum[lane];
        #pragma unroll
        for (int o = 1; o < 32; o <<= 1) {
            int y = __shfl_up_sync(0xffffffffu, s, o);
            if (lane >= o) s += y;
        }
        wsum[lane] = s;
    }
    __syncthreads();
    int excl = x - tsum + (w ? wsum[w - 1] : 0) + sbase;
    if (i < n) {
        int4 o4 = make_int4(excl, excl + v.x, excl + v.x + v.y,
                            excl + v.x + v.y + v.z);
        *(int4*)&row[i] = o4;
    }
    int ntiles = (n + 4095) >> 12;
    if (tile == ntiles - 1 && tid == 1023)
        row[n] = sbase + wsum[31];
}

// Atomic-free scatter: position = row[node] + precomputed rank.
__global__ void scatter_k(const int* __restrict__ eidx, const int* __restrict__ etype,
                          const int* __restrict__ iedge, const float* __restrict__ iw,
                          const int* __restrict__ kg_row, const int* __restrict__ kg_rk,
                          unsigned* __restrict__ kg_pk,
                          const int* __restrict__ iu_row, const int* __restrict__ iu_rk,
                          int2* __restrict__ iu_pk,
                          const int* __restrict__ ii_row, const int* __restrict__ ii_rk,
                          int2* __restrict__ ii_pk) {
    int stride = gridDim.x * blockDim.x * 4;
    for (int base = (blockIdx.x * blockDim.x + threadIdx.x) * 4; base < E_KG;
         base += stride) {
        int4 hd = *(const int4*)&eidx[base];
        int4 tl = *(const int4*)&eidx[E_KG + base];
        int4 rt = *(const int4*)&etype[base];
        int4 rk = *(const int4*)&kg_rk[base];
        int p0 = kg_row[hd.x] + rk.x;
        int p1 = kg_row[hd.y] + rk.y;
        int p2 = kg_row[hd.z] + rk.z;
        int p3 = kg_row[hd.w] + rk.w;
        kg_pk[p0] = (unsigned)tl.x | ((unsigned)(rt.x - 1) << 20);
        kg_pk[p1] = (unsigned)tl.y | ((unsigned)(rt.y - 1) << 20);
        kg_pk[p2] = (unsigned)tl.z | ((unsigned)(rt.z - 1) << 20);
        kg_pk[p3] = (unsigned)tl.w | ((unsigned)(rt.w - 1) << 20);
    }
    for (int base = (blockIdx.x * blockDim.x + threadIdx.x) * 4; base < E_IN;
         base += stride) {
        int4 u   = *(const int4*)&iedge[base];
        int4 it  = *(const int4*)&iedge[E_IN + base];
        float4 w = *(const float4*)&iw[base];
        int4 r1  = *(const int4*)&iu_rk[base];
        int4 r2  = *(const int4*)&ii_rk[base];
        int a0 = iu_row[u.x] + r1.x;
        int a1 = iu_row[u.y] + r1.y;
        int a2 = iu_row[u.z] + r1.z;
        int a3 = iu_row[u.w] + r1.w;
        int b0 = ii_row[it.x] + r2.x;
        int b1 = ii_row[it.y] + r2.y;
        int b2 = ii_row[it.z] + r2.z;
        int b3 = ii_row[it.w] + r2.w;
        iu_pk[a0] = make_int2(it.x, __float_as_int(w.x));
        iu_pk[a1] = make_int2(it.y, __float_as_int(w.y));
        iu_pk[a2] = make_int2(it.z, __float_as_int(w.z));
        iu_pk[a3] = make_int2(it.w, __float_as_int(w.w));
        ii_pk[b0] = make_int2(u.x, __float_as_int(w.x));
        ii_pk[b1] = make_int2(u.y, __float_as_int(w.y));
        ii_pk[b2] = make_int2(u.z, __float_as_int(w.z));
        ii_pk[b3] = make_int2(u.w, __float_as_int(w.w));
    }
}

// ---------------- per-layer kernels ----------------
// P[r,:] = X[r,:] @ W (64x64), output bf16. 256 threads = 16 rows x 16 col-quads.
__global__ void __launch_bounds__(256) gemm_k(const float* __restrict__ X,
                                              const float* __restrict__ W,
                                              __nv_bfloat162* __restrict__ P) {
    __shared__ float sW[64 * 64];
    __shared__ float srow[16][64];
    int tid = threadIdx.x;
    #pragma unroll
    for (int i = 0; i < 16; i++) sW[tid + i * 256] = W[tid + i * 256];
    const float4* X4 = (const float4*)(X + (size_t)blockIdx.x * 16 * 64);
    ((float4*)&srow[0][0])[tid] = X4[tid];
    __syncthreads();
    int r  = tid >> 4;
    int cq = (tid & 15) * 4;
    float4 acc = make_float4(0.f, 0.f, 0.f, 0.f);
    #pragma unroll
    for (int d = 0; d < 64; d++) {
        float a = srow[r][d];
        float4 b = *(const float4*)&sW[d * 64 + cq];
        acc.x += a * b.x; acc.y += a * b.y; acc.z += a * b.z; acc.w += a * b.w;
    }
    size_t o = ((size_t)blockIdx.x * 16 + r) * 32 + (cq >> 1);
    P[o]     = __float22bfloat162_rn(make_float2(acc.x, acc.y));
    P[o + 1] = __float22bfloat162_rn(make_float2(acc.z, acc.w));
}

__device__ __forceinline__ float4 ld_P4(const __nv_bfloat162* __restrict__ P,
                                        int row, int l) {
    uint2 raw = *(const uint2*)(P + (size_t)row * 32 + l * 2);
    __nv_bfloat162 b0 = *(__nv_bfloat162*)&raw.x;
    __nv_bfloat162 b1 = *(__nv_bfloat162*)&raw.y;
    float2 f0 = __bfloat1622float2(b0);
    float2 f1 = __bfloat1622float2(b1);
    return make_float4(f0.x, f0.y, f1.x, f1.y);
}

// Fused node update with index prefetch. Blocks [0, NB_ENT) entities,
// [NB_ENT, NB_ENT+NB_USR) users. One warp per row; lanes 0-15 edge j,
// lanes 16-31 edge j+1; lane owns dims 4*(lane&15)..+3.
template <int FINAL>
__global__ void __launch_bounds__(256) node_k(const int* __restrict__ kg_row,
                                              const unsigned* __restrict__ kg_pk,
                                              const int* __restrict__ ii_row,
                                              const int2* __restrict__ ii_pk,
                                              const int* __restrict__ iu_row,
                                              const int2* __restrict__ iu_pk,
                                              const __nv_bfloat162* __restrict__ P,
                                              const float* __restrict__ ent_cur,
                                              const float* __restrict__ usr_cur,
                                              const float* __restrict__ relemb,
                                              const float* __restrict__ ent_p0,
                                              const float* __restrict__ usr_p0,
                                              float* __restrict__ ent_out,
                                              float* __restrict__ usr_out) {
    int tid  = threadIdx.x;
    int lane = tid & 31;
    int half = lane >> 4;
    int l    = lane & 15;
    int d0   = l * 4;
    const float c3 = 1.0f / 3.0f;

    if (blockIdx.x < NB_ENT) {
        // ---------------- entity path ----------------
        __shared__ float srel[N_REL * DIMS];
        #pragma unroll
        for (int i = 0; i < 4; i++) srel[tid + i * 256] = relemb[tid + i * 256];
        __syncthreads();

        int row = blockIdx.x * 8 + (tid >> 5);
        float4 ph = ld_P4(P, row, l);

        float4 acc = make_float4(0.f, 0.f, 0.f, 0.f);
        float ssum = 0.f;
        int s = kg_row[row], e = kg_row[row + 1];
        if (s < e) {
            int i0 = s + half;
            unsigned pk = kg_pk[i0 < e ? i0 : (e - 1)];
            for (int j = s; j < e; j += 2) {
                int nj = j + 2 + half;
                unsigned pk_n = kg_pk[nj < e ? nj : (e - 1)];   // prefetch
                bool valid = (j + half) < e;
                int tl = (int)(pk & 0xFFFFFu);
                int rt = (int)(pk >> 20);
                float4 pt = ld_P4(P, tl, l);
                float4 rv = *(const float4*)&srel[rt * 64 + d0];
                float4 te = *(const float4*)&ent_cur[(size_t)tl * 64 + d0];
                float part = ph.x * pt.x * rv.x + ph.y * pt.y * rv.y
                           + ph.z * pt.z * rv.z + ph.w * pt.w * rv.w;
                part += __shfl_xor_sync(0xffffffffu, part, 1);
                part += __shfl_xor_sync(0xffffffffu, part, 2);
                part += __shfl_xor_sync(0xffffffffu, part, 4);
                float ex = valid ? __expf(part * RSQRT_DK) : 0.f;
                ssum += ex;
                acc.x += ex * te.x * rv.x;
                acc.y += ex * te.y * rv.y;
                acc.z += ex * te.z * rv.z;
                acc.w += ex * te.w * rv.w;
                pk = pk_n;
            }
        }
        acc.x += __shfl_xor_sync(0xffffffffu, acc.x, 16);
        acc.y += __shfl_xor_sync(0xffffffffu, acc.y, 16);
        acc.z += __shfl_xor_sync(0xffffffffu, acc.z, 16);
        acc.w += __shfl_xor_sync(0xffffffffu, acc.w, 16);
        ssum  += __shfl_xor_sync(0xffffffffu, ssum, 16);

        float invs = (ssum > 0.f) ? (1.f / ssum) : 1.f;
        acc.x *= invs; acc.y *= invs; acc.z *= invs; acc.w *= invs;

        float s2 = acc.x * acc.x + acc.y * acc.y + acc.z * acc.z + acc.w * acc.w;
        s2 += __shfl_xor_sync(0xffffffffu, s2, 1);
        s2 += __shfl_xor_sync(0xffffffffu, s2, 2);
        s2 += __shfl_xor_sync(0xffffffffu, s2, 4);
        s2 += __shfl_xor_sync(0xffffffffu, s2, 8);
        float invn = 1.0f / fmaxf(sqrtf(s2), 1e-12f);
        acc.x *= invn; acc.y *= invn; acc.z *= invn; acc.w *= invn;

        // user -> entity aggregation (pair-split, prefetched)
        float4 acc2 = make_float4(0.f, 0.f, 0.f, 0.f);
        int si = ii_row[row], ei = ii_row[row + 1];
        if (si < ei) {
            int i0 = si + half;
            int2 pc = ii_pk[i0 < ei ? i0 : (ei - 1)];
            for (int k = si; k < ei; k += 2) {
                int nk = k + 2 + half;
                int2 pn = ii_pk[nk < ei ? nk : (ei - 1)];       // prefetch
                bool valid = (k + half) < ei;
                float w = valid ? __int_as_float(pc.y) : 0.f;
                float4 uv = *(const float4*)&usr_cur[(size_t)pc.x * 64 + d0];
                acc2.x += w * uv.x; acc2.y += w * uv.y;
                acc2.z += w * uv.z; acc2.w += w * uv.w;
                pc = pn;
            }
        }
        acc2.x += __shfl_xor_sync(0xffffffffu, acc2.x, 16);
        acc2.y += __shfl_xor_sync(0xffffffffu, acc2.y, 16);
        acc2.z += __shfl_xor_sync(0xffffffffu, acc2.z, 16);
        acc2.w += __shfl_xor_sync(0xffffffffu, acc2.w, 16);
        acc.x += acc2.x; acc.y += acc2.y; acc.z += acc2.z; acc.w += acc2.w;

        if (half == 0) {
            if (FINAL) {
                float4 a0 = *(const float4*)&ent_cur[(size_t)row * 64 + d0];
                float4 a1 = *(const float4*)&ent_p0[(size_t)row * 64 + d0];
                acc.x = (a0.x + a1.x + acc.x) * c3;
                acc.y = (a0.y + a1.y + acc.y) * c3;
                acc.z = (a0.z + a1.z + acc.z) * c3;
                acc.w = (a0.w + a1.w + acc.w) * c3;
            }
            *(float4*)&ent_out[(size_t)row * 64 + d0] = acc;
        }
    } else {
        // ---------------- user path ----------------
        int row = (blockIdx.x - NB_ENT) * 8 + (tid >> 5);
        float4 acc = make_float4(0.f, 0.f, 0.f, 0.f);
        int s = iu_row[row], e = iu_row[row + 1];
        if (s < e) {
            int i0 = s + half;
            int2 pc = iu_pk[i0 < e ? i0 : (e - 1)];
            for (int k = s; k < e; k += 2) {
                int nk = k + 2 + half;
                int2 pn = iu_pk[nk < e ? nk : (e - 1)];          // prefetch
                bool valid = (k + half) < e;
                float w = valid ? __int_as_float(pc.y) : 0.f;
                float4 ev = *(const float4*)&ent_cur[(size_t)pc.x * 64 + d0];
                acc.x += w * ev.x; acc.y += w * ev.y;
                acc.z += w * ev.z; acc.w += w * ev.w;
                pc = pn;
            }
        }
        acc.x += __shfl_xor_sync(0xffffffffu, acc.x, 16);
        acc.y += __shfl_xor_sync(0xffffffffu, acc.y, 16);
        acc.z += __shfl_xor_sync(0xffffffffu, acc.z, 16);
        acc.w += __shfl_xor_sync(0xffffffffu, acc.w, 16);

        if (half == 0) {
            if (FINAL) {
                float4 a0 = *(const float4*)&usr_cur[(size_t)row * 64 + d0];
                float4 a1 = *(const float4*)&usr_p0[(size_t)row * 64 + d0];
                acc.x = (a0.x + a1.x + acc.x) * c3;
                acc.y = (a0.y + a1.y + acc.y) * c3;
                acc.z = (a0.z + a1.z + acc.z) * c3;
                acc.w = (a0.w + a1.w + acc.w) * c3;
            }
            *(float4*)&usr_out[(size_t)row * 64 + d0] = acc;
        }
    }
}

// ---------------- launcher ----------------
extern "C" void kernel_launch(void* const* d_in, const int* in_sizes, int n_in,
                              void* d_out, int out_size) {
    const float* user_emb   = (const float*)d_in[1];
    const float* entity_emb = (const float*)d_in[2];
    const int*   inter_edge = (const int*)d_in[3];
    const float* inter_w    = (const float*)d_in[4];
    const int*   edge_index = (const int*)d_in[5];
    const int*   edge_type  = (const int*)d_in[6];
    const float* rel_emb    = (const float*)d_in[7];
    const float* W_Q        = (const float*)d_in[8];
    float* out = (float*)d_out;
    float* out_usr = out;
    float* out_ent = out + (size_t)N_USERS * DIMS;

    __nv_bfloat162* p_P;
    float *p_ent0, *p_usr0;
    int *p_kg_row, *p_kg_cnt, *p_kg_rk, *p_iu_row, *p_iu_cnt, *p_iu_rk;
    int *p_ii_row, *p_ii_cnt, *p_ii_rk, *p_bsum;
    unsigned* p_kg_pk;
    int2 *p_iu_pk, *p_ii_pk;
    cudaGetSymbolAddress((void**)&p_P,      g_P);
    cudaGetSymbolAddress((void**)&p_ent0,   g_ent0);
    cudaGetSymbolAddress((void**)&p_usr0,   g_usr0);
    cudaGetSymbolAddress((void**)&p_kg_row, g_kg_row);
    cudaGetSymbolAddress((void**)&p_kg_cnt, g_kg_cnt);
    cudaGetSymbolAddress((void**)&p_kg_pk,  g_kg_pk);
    cudaGetSymbolAddress((void**)&p_kg_rk,  g_kg_rk);
    cudaGetSymbolAddress((void**)&p_iu_row, g_iu_row);
    cudaGetSymbolAddress((void**)&p_iu_cnt, g_iu_cnt);
    cudaGetSymbolAddress((void**)&p_iu_pk,  g_iu_pk);
    cudaGetSymbolAddress((void**)&p_iu_rk,  g_iu_rk);
    cudaGetSymbolAddress((void**)&p_ii_row, g_ii_row);
    cudaGetSymbolAddress((void**)&p_ii_cnt, g_ii_cnt);
    cudaGetSymbolAddress((void**)&p_ii_pk,  g_ii_pk);
    cudaGetSymbolAddress((void**)&p_ii_rk,  g_ii_rk);
    cudaGetSymbolAddress((void**)&p_bsum,   g_bsum);

    const int TB = 256;
    const int NB_NODE = NB_ENT + NB_USR;   // 18750

    // ---- CSR build (shared by both layers) ----
    zero_cnt_k<<<512, TB>>>(p_kg_cnt, N_ENT, p_iu_cnt, N_USERS, p_ii_cnt, N_ENT);
    hist_k<<<2048, TB>>>(edge_index, inter_edge, p_kg_cnt, p_kg_rk,
                         p_iu_cnt, p_iu_rk, p_ii_cnt, p_ii_rk);
    scanA_k<<<TOT_TILES, 1024>>>(p_kg_cnt, p_kg_row, p_iu_cnt, p_iu_row,
                                 p_ii_cnt, p_ii_row, p_bsum);
    scanC_k<<<TOT_TILES, 1024>>>(p_kg_cnt, p_kg_row, p_iu_cnt, p_iu_row,
                                 p_ii_cnt, p_ii_row, p_bsum);
    scatter_k<<<2048, TB>>>(edge_index, edge_type, inter_edge, inter_w,
                            p_kg_row, p_kg_rk, p_kg_pk,
                            p_iu_row, p_iu_rk, p_iu_pk,
                            p_ii_row, p_ii_rk, p_ii_pk);

    // ---- layer 1 ----
    gemm_k<<<N_ENT / 16, TB>>>(entity_emb, W_Q, p_P);
    node_k<0><<<NB_NODE, TB>>>(p_kg_row, p_kg_pk, p_ii_row, p_ii_pk, p_iu_row, p_iu_pk,
                               p_P, entity_emb, user_emb, rel_emb,
                               nullptr, nullptr, p_ent0, p_usr0);

    // ---- layer 2 (writes the 3-layer mean directly to out) ----
    gemm_k<<<N_ENT / 16, TB>>>(p_ent0, W_Q, p_P);
    node_k<1><<<NB_NODE, TB>>>(p_kg_row, p_kg_pk, p_ii_row, p_ii_pk, p_iu_row, p_iu_pk,
                               p_P, p_ent0, p_usr0, rel_emb,
                               entity_emb, user_emb, out_ent, out_usr);
}

// round 17
// speedup vs baseline: 1.0007x; 1.0001x over previous
#include <cuda_runtime.h>
#include <cuda_bf16.h>
#include <math.h>

#define N_USERS 50000
#define N_ENT   100000
#define DIMS    64
#define N_REL   16
#define E_KG    1500000
#define E_IN    1000000
#define RSQRT_DK 0.17677669529663687f   /* 1/sqrt(32) */

#define NB_ENT (N_ENT / 8)     /* 12500 entity blocks (8 warps = 8 rows each) */
#define NB_USR (N_USERS / 8)   /*  6250 user blocks */

// scan tiling: 1024 threads x 4 elems = 4096 per tile
#define KG_TILES 25            /* ceil(100000/4096) */
#define IU_TILES 13            /* ceil(50000/4096)  */
#define II_TILES 25
#define TOT_TILES (KG_TILES + IU_TILES + II_TILES)   /* 63 */

// ---------------- static device scratch (no runtime allocation) ----------------
__device__ __nv_bfloat162 g_P[N_ENT * 32];   // entity_emb @ W_Q, bf16 (scores only)
__device__ float g_ent0[N_ENT * DIMS];       // layer-1 entity output
__device__ float g_usr0[N_USERS * DIMS];     // layer-1 user output

// CSR structures (built once per call)
__device__ int g_kg_row[N_ENT + 1];
__device__ int g_kg_cnt[N_ENT];
__device__ unsigned g_kg_pk[E_KG];           // tail | (rel<<20)
__device__ int g_kg_rk[E_KG];                // rank within head bucket
__device__ int g_iu_row[N_USERS + 1];
__device__ int g_iu_cnt[N_USERS];
__device__ int2 g_iu_pk[E_IN];               // {item, w bits}
__device__ int g_iu_rk[E_IN];
__device__ int g_ii_row[N_ENT + 1];
__device__ int g_ii_cnt[N_ENT];
__device__ int2 g_ii_pk[E_IN];               // {user, w bits}
__device__ int g_ii_rk[E_IN];
__device__ int g_bsum[TOT_TILES];

// ---------------- CSR build ----------------
__global__ void zero_cnt_k(int* __restrict__ a, int na, int* __restrict__ b, int nb,
                           int* __restrict__ c, int nc) {
    int i = blockIdx.x * blockDim.x + threadIdx.x;
    int stride = gridDim.x * blockDim.x;
    int nab = na + nb, tot = nab + nc;
    for (; i < tot; i += stride) {
        if (i < na) a[i] = 0;
        else if (i < nab) b[i - na] = 0;
        else c[i - nab] = 0;
    }
}

// Histogram + rank: atomicAdd returns this edge's rank within its bucket.
__global__ void hist_k(const int* __restrict__ eidx, const int* __restrict__ iedge,
                       int* __restrict__ kg_cnt, int* __restrict__ kg_rk,
                       int* __restrict__ iu_cnt, int* __restrict__ iu_rk,
                       int* __restrict__ ii_cnt, int* __restrict__ ii_rk) {
    int stride = gridDim.x * blockDim.x * 4;
    for (int base = (blockIdx.x * blockDim.x + threadIdx.x) * 4; base < E_KG;
         base += stride) {
        int4 h = *(const int4*)&eidx[base];
        int4 r;
        r.x = atomicAdd(&kg_cnt[h.x], 1);
        r.y = atomicAdd(&kg_cnt[h.y], 1);
        r.z = atomicAdd(&kg_cnt[h.z], 1);
        r.w = atomicAdd(&kg_cnt[h.w], 1);
        *(int4*)&kg_rk[base] = r;
    }
    for (int base = (blockIdx.x * blockDim.x + threadIdx.x) * 4; base < E_IN;
         base += stride) {
        int4 u  = *(const int4*)&iedge[base];
        int4 it = *(const int4*)&iedge[E_IN + base];
        int4 r1, r2;
        r1.x = atomicAdd(&iu_cnt[u.x], 1);
        r1.y = atomicAdd(&iu_cnt[u.y], 1);
        r1.z = atomicAdd(&iu_cnt[u.z], 1);
        r1.w = atomicAdd(&iu_cnt[u.w], 1);
        r2.x = atomicAdd(&ii_cnt[it.x], 1);
        r2.y = atomicAdd(&ii_cnt[it.y], 1);
        r2.z = atomicAdd(&ii_cnt[it.z], 1);
        r2.w = atomicAdd(&ii_cnt[it.w], 1);
        *(int4*)&iu_rk[base] = r1;
        *(int4*)&ii_rk[base] = r2;
    }
}

// decode tile block -> (cnt, row, n, tile)
__device__ __forceinline__ void scan_decode(int b, const int* kg_cnt, int* kg_row,
                                            const int* iu_cnt, int* iu_row,
                                            const int* ii_cnt, int* ii_row,
                                            const int** cnt, int** row,
                                            int* n, int* tile) {
    if (b < KG_TILES)                { *cnt = kg_cnt; *row = kg_row; *n = N_ENT;   *tile = b; }
    else if (b < KG_TILES + IU_TILES){ *cnt = iu_cnt; *row = iu_row; *n = N_USERS; *tile = b - KG_TILES; }
    else                             { *cnt = ii_cnt; *row = ii_row; *n = N_ENT;   *tile = b - KG_TILES - IU_TILES; }
}

// Phase A: per-tile sums.
__global__ void __launch_bounds__(1024) scanA_k(const int* __restrict__ kg_cnt,
                                                int* __restrict__ kg_row,
                                                const int* __restrict__ iu_cnt,
                                                int* __restrict__ iu_row,
                                                const int* __restrict__ ii_cnt,
                                                int* __restrict__ ii_row,
                                                int* __restrict__ bsum) {
    const int* cnt; int* row; int n, tile;
    scan_decode(blockIdx.x, kg_cnt, kg_row, iu_cnt, iu_row, ii_cnt, ii_row,
                &cnt, &row, &n, &tile);
    __shared__ int wsum[32];
    int tid = threadIdx.x, lane = tid & 31, w = tid >> 5;
    int i = tile * 4096 + tid * 4;
    int4 v = (i < n) ? *(const int4*)&cnt[i] : make_int4(0, 0, 0, 0);
    int tsum = v.x + v.y + v.z + v.w;
    #pragma unroll
    for (int o = 16; o; o >>= 1) tsum += __shfl_xor_sync(0xffffffffu, tsum, o);
    if (lane == 0) wsum[w] = tsum;
    __syncthreads();
    if (w == 0) {
        int s = wsum[lane];
        #pragma unroll
        for (int o = 16; o; o >>= 1) s += __shfl_xor_sync(0xffffffffu, s, o);
        if (lane == 0) bsum[blockIdx.x] = s;
    }
}

// Phase C: per-tile exclusive scan; segment base computed inline by reducing
// the preceding tiles' sums (<= 25 values, one warp). Last tile writes row[n].
__global__ void __launch_bounds__(1024) scanC_k(const int* __restrict__ kg_cnt,
                                                int* __restrict__ kg_row,
                                                const int* __restrict__ iu_cnt,
                                                int* __restrict__ iu_row,
                                                const int* __restrict__ ii_cnt,
                                                int* __restrict__ ii_row,
                                                const int* __restrict__ bsum) {
    const int* cnt; int* row; int n, tile;
    scan_decode(blockIdx.x, kg_cnt, kg_row, iu_cnt, iu_row, ii_cnt, ii_row,
                &cnt, &row, &n, &tile);
    __shared__ int wsum[32];
    __shared__ int sbase;
    int tid = threadIdx.x, lane = tid & 31, w = tid >> 5;
    if (tid < 32) {
        int v = (tid < tile) ? bsum[blockIdx.x - tile + tid] : 0;
        #pragma unroll
        for (int o = 16; o; o >>= 1) v += __shfl_xor_sync(0xffffffffu, v, o);
        if (tid == 0) sbase = v;
    }
    int i = tile * 4096 + tid * 4;
    int4 v = (i < n) ? *(const int4*)&cnt[i] : make_int4(0, 0, 0, 0);
    int tsum = v.x + v.y + v.z + v.w;
    int x = tsum;
    #pragma unroll
    for (int o = 1; o < 32; o <<= 1) {
        int y = __shfl_up_sync(0xffffffffu, x, o);
        if (lane >= o) x += y;
    }
    if (lane == 31) wsum[w] = x;
    __syncthreads();
    if (w == 0) {
        int s = wsum[lane];
        #pragma unroll
        for (int o = 1; o < 32; o <<= 1) {
            int y = __shfl_up_sync(0xffffffffu, s, o);
            if (lane >= o) s += y;
        }
        wsum[lane] = s;
    }
    __syncthreads();
    int excl = x - tsum + (w ? wsum[w - 1] : 0) + sbase;
    if (i < n) {
        int4 o4 = make_int4(excl, excl + v.x, excl + v.x + v.y,
                            excl + v.x + v.y + v.z);
        *(int4*)&row[i] = o4;
    }
    int ntiles = (n + 4095) >> 12;
    if (tile == ntiles - 1 && tid == 1023)
        row[n] = sbase + wsum[31];
}

// Atomic-free scatter: position = row[node] + precomputed rank.
__global__ void scatter_k(const int* __restrict__ eidx, const int* __restrict__ etype,
                          const int* __restrict__ iedge, const float* __restrict__ iw,
                          const int* __restrict__ kg_row, const int* __restrict__ kg_rk,
                          unsigned* __restrict__ kg_pk,
                          const int* __restrict__ iu_row, const int* __restrict__ iu_rk,
                          int2* __restrict__ iu_pk,
                          const int* __restrict__ ii_row, const int* __restrict__ ii_rk,
                          int2* __restrict__ ii_pk) {
    int stride = gridDim.x * blockDim.x * 4;
    for (int base = (blockIdx.x * blockDim.x + threadIdx.x) * 4; base < E_KG;
         base += stride) {
        int4 hd = *(const int4*)&eidx[base];
        int4 tl = *(const int4*)&eidx[E_KG + base];
        int4 rt = *(const int4*)&etype[base];
        int4 rk = *(const int4*)&kg_rk[base];
        int p0 = kg_row[hd.x] + rk.x;
        int p1 = kg_row[hd.y] + rk.y;
        int p2 = kg_row[hd.z] + rk.z;
        int p3 = kg_row[hd.w] + rk.w;
        kg_pk[p0] = (unsigned)tl.x | ((unsigned)(rt.x - 1) << 20);
        kg_pk[p1] = (unsigned)tl.y | ((unsigned)(rt.y - 1) << 20);
        kg_pk[p2] = (unsigned)tl.z | ((unsigned)(rt.z - 1) << 20);
        kg_pk[p3] = (unsigned)tl.w | ((unsigned)(rt.w - 1) << 20);
    }
    for (int base = (blockIdx.x * blockDim.x + threadIdx.x) * 4; base < E_IN;
         base += stride) {
        int4 u   = *(const int4*)&iedge[base];
        int4 it  = *(const int4*)&iedge[E_IN + base];
        float4 w = *(const float4*)&iw[base];
        int4 r1  = *(const int4*)&iu_rk[base];
        int4 r2  = *(const int4*)&ii_rk[base];
        int a0 = iu_row[u.x] + r1.x;
        int a1 = iu_row[u.y] + r1.y;
        int a2 = iu_row[u.z] + r1.z;
        int a3 = iu_row[u.w] + r1.w;
        int b0 = ii_row[it.x] + r2.x;
        int b1 = ii_row[it.y] + r2.y;
        int b2 = ii_row[it.z] + r2.z;
        int b3 = ii_row[it.w] + r2.w;
        iu_pk[a0] = make_int2(it.x, __float_as_int(w.x));
        iu_pk[a1] = make_int2(it.y, __float_as_int(w.y));
        iu_pk[a2] = make_int2(it.z, __float_as_int(w.z));
        iu_pk[a3] = make_int2(it.w, __float_as_int(w.w));
        ii_pk[b0] = make_int2(u.x, __float_as_int(w.x));
        ii_pk[b1] = make_int2(u.y, __float_as_int(w.y));
        ii_pk[b2] = make_int2(u.z, __float_as_int(w.z));
        ii_pk[b3] = make_int2(u.w, __float_as_int(w.w));
    }
}

// ---------------- per-layer kernels ----------------
// P[r,:] = X[r,:] @ W (64x64), output bf16. 256 threads = 16 rows x 16 col-quads.
__global__ void __launch_bounds__(256) gemm_k(const float* __restrict__ X,
                                              const float* __restrict__ W,
                                              __nv_bfloat162* __restrict__ P) {
    __shared__ float sW[64 * 64];
    __shared__ float srow[16][64];
    int tid = threadIdx.x;
    #pragma unroll
    for (int i = 0; i < 16; i++) sW[tid + i * 256] = W[tid + i * 256];
    const float4* X4 = (const float4*)(X + (size_t)blockIdx.x * 16 * 64);
    ((float4*)&srow[0][0])[tid] = X4[tid];
    __syncthreads();
    int r  = tid >> 4;
    int cq = (tid & 15) * 4;
    float4 acc = make_float4(0.f, 0.f, 0.f, 0.f);
    #pragma unroll
    for (int d = 0; d < 64; d++) {
        float a = srow[r][d];
        float4 b = *(const float4*)&sW[d * 64 + cq];
        acc.x += a * b.x; acc.y += a * b.y; acc.z += a * b.z; acc.w += a * b.w;
    }
    size_t o = ((size_t)blockIdx.x * 16 + r) * 32 + (cq >> 1);
    P[o]     = __float22bfloat162_rn(make_float2(acc.x, acc.y));
    P[o + 1] = __float22bfloat162_rn(make_float2(acc.z, acc.w));
}

__device__ __forceinline__ float4 ld_P4(const __nv_bfloat162* __restrict__ P,
                                        int row, int l) {
    uint2 raw = *(const uint2*)(P + (size_t)row * 32 + l * 2);
    __nv_bfloat162 b0 = *(__nv_bfloat162*)&raw.x;
    __nv_bfloat162 b1 = *(__nv_bfloat162*)&raw.y;
    float2 f0 = __bfloat1622float2(b0);
    float2 f1 = __bfloat1622float2(b1);
    return make_float4(f0.x, f0.y, f1.x, f1.y);
}

// Fused node update with index prefetch. Blocks [0, NB_ENT) entities,
// [NB_ENT, NB_ENT+NB_USR) users. One warp per row; lanes 0-15 edge j,
// lanes 16-31 edge j+1; lane owns dims 4*(lane&15)..+3.
template <int FINAL>
__global__ void __launch_bounds__(256) node_k(const int* __restrict__ kg_row,
                                              const unsigned* __restrict__ kg_pk,
                                              const int* __restrict__ ii_row,
                                              const int2* __restrict__ ii_pk,
                                              const int* __restrict__ iu_row,
                                              const int2* __restrict__ iu_pk,
                                              const __nv_bfloat162* __restrict__ P,
                                              const float* __restrict__ ent_cur,
                                              const float* __restrict__ usr_cur,
                                              const float* __restrict__ relemb,
                                              const float* __restrict__ ent_p0,
                                              const float* __restrict__ usr_p0,
                                              float* __restrict__ ent_out,
                                              float* __restrict__ usr_out) {
    int tid  = threadIdx.x;
    int lane = tid & 31;
    int half = lane >> 4;
    int l    = lane & 15;
    int d0   = l * 4;
    const float c3 = 1.0f / 3.0f;

    if (blockIdx.x < NB_ENT) {
        // ---------------- entity path ----------------
        __shared__ float srel[N_REL * DIMS];
        #pragma unroll
        for (int i = 0; i < 4; i++) srel[tid + i * 256] = relemb[tid + i * 256];
        __syncthreads();

        int row = blockIdx.x * 8 + (tid >> 5);
        float4 ph = ld_P4(P, row, l);

        float4 acc = make_float4(0.f, 0.f, 0.f, 0.f);
        float ssum = 0.f;
        int s = kg_row[row], e = kg_row[row + 1];
        if (s < e) {
            int i0 = s + half;
            unsigned pk = kg_pk[i0 < e ? i0 : (e - 1)];
            for (int j = s; j < e; j += 2) {
                int nj = j + 2 + half;
                unsigned pk_n = kg_pk[nj < e ? nj : (e - 1)];   // prefetch
                bool valid = (j + half) < e;
                int tl = (int)(pk & 0xFFFFFu);
                int rt = (int)(pk >> 20);
                float4 pt = ld_P4(P, tl, l);
                float4 rv = *(const float4*)&srel[rt * 64 + d0];
                float4 te = *(const float4*)&ent_cur[(size_t)tl * 64 + d0];
                float part = ph.x * pt.x * rv.x + ph.y * pt.y * rv.y
                           + ph.z * pt.z * rv.z + ph.w * pt.w * rv.w;
                part += __shfl_xor_sync(0xffffffffu, part, 1);
                part += __shfl_xor_sync(0xffffffffu, part, 2);
                part += __shfl_xor_sync(0xffffffffu, part, 4);
                float ex = valid ? __expf(part * RSQRT_DK) : 0.f;
                ssum += ex;
                acc.x += ex * te.x * rv.x;
                acc.y += ex * te.y * rv.y;
                acc.z += ex * te.z * rv.z;
                acc.w += ex * te.w * rv.w;
                pk = pk_n;
            }
        }
        acc.x += __shfl_xor_sync(0xffffffffu, acc.x, 16);
        acc.y += __shfl_xor_sync(0xffffffffu, acc.y, 16);
        acc.z += __shfl_xor_sync(0xffffffffu, acc.z, 16);
        acc.w += __shfl_xor_sync(0xffffffffu, acc.w, 16);
        ssum  += __shfl_xor_sync(0xffffffffu, ssum, 16);

        float invs = (ssum > 0.f) ? (1.f / ssum) : 1.f;
        acc.x *= invs; acc.y *= invs; acc.z *= invs; acc.w *= invs;

        float s2 = acc.x * acc.x + acc.y * acc.y + acc.z * acc.z + acc.w * acc.w;
        s2 += __shfl_xor_sync(0xffffffffu, s2, 1);
        s2 += __shfl_xor_sync(0xffffffffu, s2, 2);
        s2 += __shfl_xor_sync(0xffffffffu, s2, 4);
        s2 += __shfl_xor_sync(0xffffffffu, s2, 8);
        float invn = 1.0f / fmaxf(sqrtf(s2), 1e-12f);
        acc.x *= invn; acc.y *= invn; acc.z *= invn; acc.w *= invn;

        // user -> entity aggregation (pair-split, prefetched)
        float4 acc2 = make_float4(0.f, 0.f, 0.f, 0.f);
        int si = ii_row[row], ei = ii_row[row + 1];
        if (si < ei) {
            int i0 = si + half;
            int2 pc = ii_pk[i0 < ei ? i0 : (ei - 1)];
            for (int k = si; k < ei; k += 2) {
                int nk = k + 2 + half;
                int2 pn = ii_pk[nk < ei ? nk : (ei - 1)];       // prefetch
                bool valid = (k + half) < ei;
                float w = valid ? __int_as_float(pc.y) : 0.f;
                float4 uv = *(const float4*)&usr_cur[(size_t)pc.x * 64 + d0];
                acc2.x += w * uv.x; acc2.y += w * uv.y;
                acc2.z += w * uv.z; acc2.w += w * uv.w;
                pc = pn;
            }
        }
        acc2.x += __shfl_xor_sync(0xffffffffu, acc2.x, 16);
        acc2.y += __shfl_xor_sync(0xffffffffu, acc2.y, 16);
        acc2.z += __shfl_xor_sync(0xffffffffu, acc2.z, 16);
        acc2.w += __shfl_xor_sync(0xffffffffu, acc2.w, 16);
        acc.x += acc2.x; acc.y += acc2.y; acc.z += acc2.z; acc.w += acc2.w;

        if (half == 0) {
            if (FINAL) {
                float4 a0 = *(const float4*)&ent_cur[(size_t)row * 64 + d0];
                float4 a1 = *(const float4*)&ent_p0[(size_t)row * 64 + d0];
                acc.x = (a0.x + a1.x + acc.x) * c3;
                acc.y = (a0.y + a1.y + acc.y) * c3;
                acc.z = (a0.z + a1.z + acc.z) * c3;
                acc.w = (a0.w + a1.w + acc.w) * c3;
            }
            *(float4*)&ent_out[(size_t)row * 64 + d0] = acc;
        }
    } else {
        // ---------------- user path ----------------
        int row = (blockIdx.x - NB_ENT) * 8 + (tid >> 5);
        float4 acc = make_float4(0.f, 0.f, 0.f, 0.f);
        int s = iu_row[row], e = iu_row[row + 1];
        if (s < e) {
            int i0 = s + half;
            int2 pc = iu_pk[i0 < e ? i0 : (e - 1)];
            for (int k = s; k < e; k += 2) {
                int nk = k + 2 + half;
                int2 pn = iu_pk[nk < e ? nk : (e - 1)];          // prefetch
                bool valid = (k + half) < e;
                float w = valid ? __int_as_float(pc.y) : 0.f;
                float4 ev = *(const float4*)&ent_cur[(size_t)pc.x * 64 + d0];
                acc.x += w * ev.x; acc.y += w * ev.y;
                acc.z += w * ev.z; acc.w += w * ev.w;
                pc = pn;
            }
        }
        acc.x += __shfl_xor_sync(0xffffffffu, acc.x, 16);
        acc.y += __shfl_xor_sync(0xffffffffu, acc.y, 16);
        acc.z += __shfl_xor_sync(0xffffffffu, acc.z, 16);
        acc.w += __shfl_xor_sync(0xffffffffu, acc.w, 16);

        if (half == 0) {
            if (FINAL) {
                float4 a0 = *(const float4*)&usr_cur[(size_t)row * 64 + d0];
                float4 a1 = *(const float4*)&usr_p0[(size_t)row * 64 + d0];
                acc.x = (a0.x + a1.x + acc.x) * c3;
                acc.y = (a0.y + a1.y + acc.y) * c3;
                acc.z = (a0.z + a1.z + acc.z) * c3;
                acc.w = (a0.w + a1.w + acc.w) * c3;
            }
            *(float4*)&usr_out[(size_t)row * 64 + d0] = acc;
        }
    }
}

// ---------------- launcher ----------------
extern "C" void kernel_launch(void* const* d_in, const int* in_sizes, int n_in,
                              void* d_out, int out_size) {
    const float* user_emb   = (const float*)d_in[1];
    const float* entity_emb = (const float*)d_in[2];
    const int*   inter_edge = (const int*)d_in[3];
    const float* inter_w    = (const float*)d_in[4];
    const int*   edge_index = (const int*)d_in[5];
    const int*   edge_type  = (const int*)d_in[6];
    const float* rel_emb    = (const float*)d_in[7];
    const float* W_Q        = (const float*)d_in[8];
    float* out = (float*)d_out;
    float* out_usr = out;
    float* out_ent = out + (size_t)N_USERS * DIMS;

    __nv_bfloat162* p_P;
    float *p_ent0, *p_usr0;
    int *p_kg_row, *p_kg_cnt, *p_kg_rk, *p_iu_row, *p_iu_cnt, *p_iu_rk;
    int *p_ii_row, *p_ii_cnt, *p_ii_rk, *p_bsum;
    unsigned* p_kg_pk;
    int2 *p_iu_pk, *p_ii_pk;
    cudaGetSymbolAddress((void**)&p_P,      g_P);
    cudaGetSymbolAddress((void**)&p_ent0,   g_ent0);
    cudaGetSymbolAddress((void**)&p_usr0,   g_usr0);
    cudaGetSymbolAddress((void**)&p_kg_row, g_kg_row);
    cudaGetSymbolAddress((void**)&p_kg_cnt, g_kg_cnt);
    cudaGetSymbolAddress((void**)&p_kg_pk,  g_kg_pk);
    cudaGetSymbolAddress((void**)&p_kg_rk,  g_kg_rk);
    cudaGetSymbolAddress((void**)&p_iu_row, g_iu_row);
    cudaGetSymbolAddress((void**)&p_iu_cnt, g_iu_cnt);
    cudaGetSymbolAddress((void**)&p_iu_pk,  g_iu_pk);
    cudaGetSymbolAddress((void**)&p_iu_rk,  g_iu_rk);
    cudaGetSymbolAddress((void**)&p_ii_row, g_ii_row);
    cudaGetSymbolAddress((void**)&p_ii_cnt, g_ii_cnt);
    cudaGetSymbolAddress((void**)&p_ii_pk,  g_ii_pk);
    cudaGetSymbolAddress((void**)&p_ii_rk,  g_ii_rk);
    cudaGetSymbolAddress((void**)&p_bsum,   g_bsum);

    const int TB = 256;
    const int NB_NODE = NB_ENT + NB_USR;   // 18750

    // ---- CSR build (shared by both layers) ----
    zero_cnt_k<<<512, TB>>>(p_kg_cnt, N_ENT, p_iu_cnt, N_USERS, p_ii_cnt, N_ENT);
    hist_k<<<2048, TB>>>(edge_index, inter_edge, p_kg_cnt, p_kg_rk,
                         p_iu_cnt, p_iu_rk, p_ii_cnt, p_ii_rk);
    scanA_k<<<TOT_TILES, 1024>>>(p_kg_cnt, p_kg_row, p_iu_cnt, p_iu_row,
                                 p_ii_cnt, p_ii_row, p_bsum);
    scanC_k<<<TOT_TILES, 1024>>>(p_kg_cnt, p_kg_row, p_iu_cnt, p_iu_row,
                                 p_ii_cnt, p_ii_row, p_bsum);
    scatter_k<<<2048, TB>>>(edge_index, edge_type, inter_edge, inter_w,
                            p_kg_row, p_kg_rk, p_kg_pk,
                            p_iu_row, p_iu_rk, p_iu_pk,
                            p_ii_row, p_ii_rk, p_ii_pk);

    // ---- layer 1 ----
    gemm_k<<<N_ENT / 16, TB>>>(entity_emb, W_Q, p_P);
    node_k<0><<<NB_NODE, TB>>>(p_kg_row, p_kg_pk, p_ii_row, p_ii_pk, p_iu_row, p_iu_pk,
                               p_P, entity_emb, user_emb, rel_emb,
                               nullptr, nullptr, p_ent0, p_usr0);

    // ---- layer 2 (writes the 3-layer mean directly to out) ----
    gemm_k<<<N_ENT / 16, TB>>>(p_ent0, W_Q, p_P);
    node_k<1><<<NB_NODE, TB>>>(p_kg_row, p_kg_pk, p_ii_row, p_ii_pk, p_iu_row, p_iu_pk,
                               p_P, p_ent0, p_usr0, rel_emb,
                               entity_emb, user_emb, out_ent, out_usr);
}